// round 6
// baseline (speedup 1.0000x reference)
#include <cuda_runtime.h>
#include <cuda_bf16.h>
#include <math.h>

// Problem dims
#define Tt 16
#define Mm 1024
#define Hh 128
#define ROWS 16384
#define MAXD 128
#define NL_TR 5
#define NCTA 148

// ---------------- scratch (device globals) ----------------
__device__ float g_h[ROWS * 512];          // GAT projections (512) / transformer QKV (384) fp32
__device__ float g_ss[ROWS * 4];
__device__ float g_sd[ROWS * 4];
__device__ unsigned char g_m[ROWS];
__device__ int g_cnt[ROWS];
__device__ unsigned short g_nbr[ROWS * MAXD];
__device__ float g_xs[ROWS * Hh];
__device__ __nv_bfloat16 g_xah[ROWS * Hh], g_xal[ROWS * Hh];
__device__ __nv_bfloat16 g_xbh[ROWS * Hh], g_xbl[ROWS * Hh];
__device__ __nv_bfloat16 g_xsh[ROWS * Hh], g_xsl[ROWS * Hh];
__device__ __nv_bfloat16 g_atth[ROWS * Hh], g_attl[ROWS * Hh];
__device__ __nv_bfloat16 g_ffh[ROWS * 512], g_ffl[ROWS * 512];

#define WTOT 1310720
#define OFF_GAT 0
#define OFF_QKV 327680
#define OFF_WO  573440
#define OFF_FF1 655360
#define OFF_FF2 983040
__device__ __nv_bfloat16 g_wh[WTOT];
__device__ __nv_bfloat16 g_wl[WTOT];

// global barrier state
__device__ unsigned g_barcnt;
__device__ unsigned g_barphase;

__device__ __forceinline__ void gsync(unsigned* sph) {
    __syncthreads();
    if (threadIdx.x == 0) {
        unsigned target = *sph + 1;
        __threadfence();
        unsigned old = atomicAdd(&g_barcnt, 1);
        if (old == gridDim.x - 1) {
            g_barcnt = 0;
            __threadfence();
            *(volatile unsigned*)&g_barphase = target;
        } else {
            while (*(volatile unsigned*)&g_barphase != target) { }
            __threadfence();
        }
        *sph = target;
    }
    __syncthreads();
}

__device__ __forceinline__ unsigned smem_u32(const void* p) {
    unsigned a;
    asm("{ .reg .u64 t; cvta.to.shared.u64 t, %1; cvt.u32.u64 %0, t; }" : "=r"(a) : "l"(p));
    return a;
}
__device__ __forceinline__ void ldmat4(unsigned& r0, unsigned& r1, unsigned& r2, unsigned& r3, unsigned addr) {
    asm volatile("ldmatrix.sync.aligned.m8n8.x4.shared.b16 {%0,%1,%2,%3}, [%4];"
        : "=r"(r0), "=r"(r1), "=r"(r2), "=r"(r3) : "r"(addr));
}
__device__ __forceinline__ void mma16816(float* c, unsigned a0, unsigned a1, unsigned a2, unsigned a3,
                                         unsigned b0, unsigned b1) {
    asm volatile("mma.sync.aligned.m16n8k16.row.col.f32.bf16.bf16.f32 "
        "{%0,%1,%2,%3}, {%4,%5,%6,%7}, {%8,%9}, {%0,%1,%2,%3};"
        : "+f"(c[0]), "+f"(c[1]), "+f"(c[2]), "+f"(c[3])
        : "r"(a0), "r"(a1), "r"(a2), "r"(a3), "r"(b0), "r"(b1));
}
__device__ __forceinline__ void cpa16(unsigned dst, const void* src) {
    asm volatile("cp.async.ca.shared.global [%0], [%1], 16;" :: "r"(dst), "l"(src));
}
#define CPA_COMMIT() asm volatile("cp.async.commit_group;" ::: "memory")
#define CPA_WAIT1() asm volatile("cp.async.wait_group 1;" ::: "memory")
#define CPA_WAIT0() asm volatile("cp.async.wait_group 0;" ::: "memory")

__device__ __forceinline__ unsigned pack_hi2(float a, float b) {
    __nv_bfloat16 ha = __float2bfloat16(a), hb = __float2bfloat16(b);
    return (unsigned)__bfloat16_as_ushort(ha) | ((unsigned)__bfloat16_as_ushort(hb) << 16);
}
__device__ __forceinline__ unsigned pack_lo2(float a, float b) {
    __nv_bfloat16 ha = __float2bfloat16(a), hb = __float2bfloat16(b);
    float la = a - __bfloat162float(ha), lb2 = b - __bfloat162float(hb);
    __nv_bfloat16 qa = __float2bfloat16(la), qb = __float2bfloat16(lb2);
    return (unsigned)__bfloat16_as_ushort(qa) | ((unsigned)__bfloat16_as_ushort(qb) << 16);
}

// SMEM: 2 stages x 4 planes, each 128 rows x 64 bf16 (144B stride)
#define TROW 144
#define PBUF (128 * TROW)
#define STAGE (4 * PBUF)
#define P_AHI 0
#define P_ALO PBUF
#define P_BHI (2 * PBUF)
#define P_BLO (3 * PBUF)
#define GSM_TOTAL (2 * STAGE)   // 147456

// ---------------- GEMM phase (persistent tiles) ----------------
template <int ACT, bool RESID, bool SCORES, bool LNORM>
__device__ void gemm_phase(char* smem,
        const __nv_bfloat16* __restrict__ Ah, const __nv_bfloat16* __restrict__ Al,
        const __nv_bfloat16* __restrict__ Bh, const __nv_bfloat16* __restrict__ Bl,
        const float* __restrict__ bias, const float* __restrict__ Rr,
        float* __restrict__ C, __nv_bfloat16* __restrict__ Ch, __nv_bfloat16* __restrict__ Cl,
        const float* __restrict__ asrc, const float* __restrict__ adst,
        float* __restrict__ gss, float* __restrict__ gsd,
        const float* __restrict__ ls, const float* __restrict__ lb,
        int ntx, int Nt, int Kt) {
    const unsigned sb = smem_u32(smem);
    const int tid = threadIdx.x;
    const int wid = tid >> 5, lane = tid & 31;
    const int wr = wid >> 1, wc = wid & 1;
    const int ltile = lane >> 3, lrow = lane & 7;
    const int nch = Kt >> 6;
    const int njobs = ntx * (ROWS / 128);

    for (int job = blockIdx.x; job < njobs; job += gridDim.x) {
        const int bx = job % ntx;
        const int by = job / ntx;
        const int row0 = by * 128;
        const int col0 = bx * 128;

        float acc[2][8][4];
#pragma unroll
        for (int mt = 0; mt < 2; mt++)
#pragma unroll
            for (int nt = 0; nt < 8; nt++)
#pragma unroll
                for (int e = 0; e < 4; e++) acc[mt][nt][e] = 0.f;

#define LOAD_CHUNK(cidx, s) do { \
    unsigned base = sb + (s) * STAGE; \
    _Pragma("unroll") \
    for (int j = 0; j < 4; j++) { \
        int i = tid + j * 256; \
        int rr = i >> 3, qq = i & 7; \
        unsigned off = (unsigned)(rr * TROW + qq * 16); \
        size_t ga = (size_t)(row0 + rr) * Kt + (cidx) * 64 + qq * 8; \
        size_t gb = (size_t)(col0 + rr) * Kt + (cidx) * 64 + qq * 8; \
        cpa16(base + P_AHI + off, Ah + ga); \
        cpa16(base + P_ALO + off, Al + ga); \
        cpa16(base + P_BHI + off, Bh + gb); \
        cpa16(base + P_BLO + off, Bl + gb); \
    } \
} while (0)

        LOAD_CHUNK(0, 0);
        CPA_COMMIT();

        for (int c = 0; c < nch; c++) {
            if (c + 1 < nch) {
                LOAD_CHUNK(c + 1, (c + 1) & 1);
                CPA_COMMIT();
                CPA_WAIT1();
            } else {
                CPA_WAIT0();
            }
            __syncthreads();
            unsigned base = sb + (c & 1) * STAGE;
#pragma unroll
            for (int ks = 0; ks < 4; ks++) {
                unsigned ah[2][4], al[2][4];
#pragma unroll
                for (int mt = 0; mt < 2; mt++) {
                    int row = wr * 32 + mt * 16 + lrow + (ltile & 1) * 8;
                    int kcol = ks * 16 + (ltile >> 1) * 8;
                    unsigned off = (unsigned)(row * TROW + kcol * 2);
                    ldmat4(ah[mt][0], ah[mt][1], ah[mt][2], ah[mt][3], base + P_AHI + off);
                    ldmat4(al[mt][0], al[mt][1], al[mt][2], al[mt][3], base + P_ALO + off);
                }
#pragma unroll
                for (int g = 0; g < 4; g++) {
                    int n = wc * 64 + g * 16 + lrow + (ltile >> 1) * 8;
                    int kcol = ks * 16 + (ltile & 1) * 8;
                    unsigned off = (unsigned)(n * TROW + kcol * 2);
                    unsigned bh[4], bl[4];
                    ldmat4(bh[0], bh[1], bh[2], bh[3], base + P_BHI + off);
                    ldmat4(bl[0], bl[1], bl[2], bl[3], base + P_BLO + off);
#pragma unroll
                    for (int mt = 0; mt < 2; mt++)
#pragma unroll
                        for (int half = 0; half < 2; half++) {
                            float* cc = acc[mt][g * 2 + half];
                            mma16816(cc, ah[mt][0], ah[mt][1], ah[mt][2], ah[mt][3],
                                     bh[half * 2], bh[half * 2 + 1]);
                            mma16816(cc, ah[mt][0], ah[mt][1], ah[mt][2], ah[mt][3],
                                     bl[half * 2], bl[half * 2 + 1]);
                            mma16816(cc, al[mt][0], al[mt][1], al[mt][2], al[mt][3],
                                     bh[half * 2], bh[half * 2 + 1]);
                        }
                }
            }
            __syncthreads();
        }
#undef LOAD_CHUNK

        float* stage = (float*)smem;
#pragma unroll
        for (int mt = 0; mt < 2; mt++)
#pragma unroll
            for (int nt = 0; nt < 8; nt++) {
                int row = wr * 32 + mt * 16 + (lane >> 2);
                int col = wc * 64 + nt * 8 + (lane & 3) * 2;
                float2 v0 = make_float2(acc[mt][nt][0], acc[mt][nt][1]);
                float2 v1 = make_float2(acc[mt][nt][2], acc[mt][nt][3]);
                *(float2*)(stage + (size_t)row * 132 + col) = v0;
                *(float2*)(stage + (size_t)(row + 8) * 132 + col) = v1;
            }
        __syncthreads();

        if (LNORM) {
            const int c = lane * 4;
            float4 bb = *(const float4*)(bias + c);
            float4 sv = *(const float4*)(ls + c);
            float4 bv = *(const float4*)(lb + c);
#pragma unroll 4
            for (int rr = 0; rr < 16; rr++) {
                int r = wid * 16 + rr;
                float4 v = *(float4*)(stage + (size_t)r * 132 + c);
                float4 res = *(const float4*)(Rr + (size_t)(row0 + r) * 128 + c);
                v.x += bb.x + res.x; v.y += bb.y + res.y;
                v.z += bb.z + res.z; v.w += bb.w + res.w;
                float s = v.x + v.y + v.z + v.w;
#pragma unroll
                for (int o = 16; o; o >>= 1) s += __shfl_xor_sync(0xFFFFFFFFu, s, o);
                float mean = s * (1.f / 128.f);
                float dx = v.x - mean, dy = v.y - mean, dz = v.z - mean, dw = v.w - mean;
                float qq = dx * dx + dy * dy + dz * dz + dw * dw;
#pragma unroll
                for (int o = 16; o; o >>= 1) qq += __shfl_xor_sync(0xFFFFFFFFu, qq, o);
                float rstd = rsqrtf(qq * (1.f / 128.f) + 1e-5f);
                float4 ov;
                ov.x = dx * rstd * sv.x + bv.x;
                ov.y = dy * rstd * sv.y + bv.y;
                ov.z = dz * rstd * sv.z + bv.z;
                ov.w = dw * rstd * sv.w + bv.w;
                if (C) *(float4*)(C + (size_t)(row0 + r) * 128 + c) = ov;
                if (Ch) {
                    uint2 uh, ul;
                    uh.x = pack_hi2(ov.x, ov.y); uh.y = pack_hi2(ov.z, ov.w);
                    ul.x = pack_lo2(ov.x, ov.y); ul.y = pack_lo2(ov.z, ov.w);
                    *(uint2*)(Ch + (size_t)(row0 + r) * 128 + c) = uh;
                    *(uint2*)(Cl + (size_t)(row0 + r) * 128 + c) = ul;
                }
            }
        } else {
            for (int i = tid; i < 128 * 32; i += 256) {
                int r = i >> 5, q = i & 31;
                int c = q * 4;
                float4 v = *(float4*)(stage + (size_t)r * 132 + c);
                if (bias) {
                    v.x += bias[col0 + c];
                    v.y += bias[col0 + c + 1];
                    v.z += bias[col0 + c + 2];
                    v.w += bias[col0 + c + 3];
                }
                if (RESID) {
                    float4 rr = *(const float4*)(Rr + (size_t)(row0 + r) * Nt + col0 + c);
                    v.x += rr.x; v.y += rr.y; v.z += rr.z; v.w += rr.w;
                }
                if (ACT == 1) {
                    v.x = fmaxf(v.x, 0.f); v.y = fmaxf(v.y, 0.f);
                    v.z = fmaxf(v.z, 0.f); v.w = fmaxf(v.w, 0.f);
                }
                if (C) *(float4*)(C + (size_t)(row0 + r) * Nt + col0 + c) = v;
                if (Ch) {
                    uint2 uh, ul;
                    uh.x = pack_hi2(v.x, v.y); uh.y = pack_hi2(v.z, v.w);
                    ul.x = pack_lo2(v.x, v.y); ul.y = pack_lo2(v.z, v.w);
                    *(uint2*)(Ch + (size_t)(row0 + r) * Nt + col0 + c) = uh;
                    *(uint2*)(Cl + (size_t)(row0 + r) * Nt + col0 + c) = ul;
                }
            }
        }

        if (SCORES && tid < 128) {
            int r = tid;
            float s1 = 0.f, s2 = 0.f;
            const float* as = asrc + col0;
            const float* ad = adst + col0;
            const float* sp = stage + (size_t)r * 132;
#pragma unroll 8
            for (int c = 0; c < 128; c++) {
                float hv = sp[c];
                s1 += hv * as[c];
                s2 += hv * ad[c];
            }
            gss[(size_t)(row0 + r) * 4 + bx] = s1;
            gsd[(size_t)(row0 + r) * 4 + bx] = s2;
        }
        __syncthreads();
    }
}

// ---------------- GAT aggregation phase (2 rows per CTA job) ----------------
__device__ void agg_phase(char* smem, const float* __restrict__ bias,
                          __nv_bfloat16* __restrict__ xh, __nv_bfloat16* __restrict__ xl) {
    const int tid = threadIdx.x;
    const int h2 = tid >> 7;
    const int t2 = tid & 127;
    unsigned short* nb = (unsigned short*)smem + h2 * 128;
    float* wsh = (float*)(smem + 512) + h2 * 512;     // [4][128]

    for (int job = blockIdx.x; job < ROWS / 2; job += gridDim.x) {
        int row = job * 2 + h2;
        int t = row >> 10;
        bool alive = g_m[row] != 0;
        int cnt = alive ? g_cnt[row] : 0;
        if (cnt > MAXD) cnt = MAXD;
        if (t2 < cnt) nb[t2] = g_nbr[(size_t)row * MAXD + t2];

        if (t2 < cnt) {
            int jr = (t << 10) + nb[t2];
#pragma unroll
            for (int hh = 0; hh < 4; hh++) {
                float z = g_sd[row * 4 + hh] + g_ss[jr * 4 + hh];
                wsh[hh * 128 + t2] = (z > 0.f) ? z : 0.2f * z;
            }
        } else {
#pragma unroll
            for (int hh = 0; hh < 4; hh++) wsh[hh * 128 + t2] = -INFINITY;
        }
        __syncthreads();

        {
            int head = (tid >> 5) & 3;
            int lane = tid & 31;
            float* wrow = wsh + head * 128;
            float v0 = wrow[lane], v1 = wrow[lane + 32], v2 = wrow[lane + 64], v3 = wrow[lane + 96];
            float mx = fmaxf(fmaxf(v0, v1), fmaxf(v2, v3));
#pragma unroll
            for (int o = 16; o; o >>= 1) mx = fmaxf(mx, __shfl_xor_sync(0xFFFFFFFFu, mx, o));
            float e0 = expf(v0 - mx), e1 = expf(v1 - mx), e2 = expf(v2 - mx), e3 = expf(v3 - mx);
            float s = e0 + e1 + e2 + e3;
#pragma unroll
            for (int o = 16; o; o >>= 1) s += __shfl_xor_sync(0xFFFFFFFFu, s, o);
            float inv = 1.f / s;
            wrow[lane] = e0 * inv;
            wrow[lane + 32] = e1 * inv;
            wrow[lane + 64] = e2 * inv;
            wrow[lane + 96] = e3 * inv;
        }
        __syncthreads();

        float out = 0.f;
        if (alive) {
            float acc0 = 0.f, acc1 = 0.f, acc2 = 0.f, acc3 = 0.f;
            const float* hbase = g_h + (((size_t)(t << 10)) << 9) + t2;
            int j = 0;
            for (; j + 4 <= cnt; j += 4) {
                const float* p0 = hbase + ((size_t)nb[j] << 9);
                const float* p1 = hbase + ((size_t)nb[j + 1] << 9);
                const float* p2 = hbase + ((size_t)nb[j + 2] << 9);
                const float* p3 = hbase + ((size_t)nb[j + 3] << 9);
#pragma unroll
                for (int hh = 0; hh < 4; hh++) {
                    acc0 += wsh[hh * 128 + j] * p0[hh << 7];
                    acc1 += wsh[hh * 128 + j + 1] * p1[hh << 7];
                    acc2 += wsh[hh * 128 + j + 2] * p2[hh << 7];
                    acc3 += wsh[hh * 128 + j + 3] * p3[hh << 7];
                }
            }
            for (; j < cnt; j++) {
                const float* p0 = hbase + ((size_t)nb[j] << 9);
#pragma unroll
                for (int hh = 0; hh < 4; hh++) acc0 += wsh[hh * 128 + j] * p0[hh << 7];
            }
            out = fmaxf((acc0 + acc1 + acc2 + acc3) * 0.25f + bias[t2], 0.f);
        }
        __nv_bfloat16 hi = __float2bfloat16(out);
        xh[(size_t)row * 128 + t2] = hi;
        xl[(size_t)row * 128 + t2] = __float2bfloat16(out - __bfloat162float(hi));
        __syncthreads();
    }
}

// ---------------- attention phase (2 sequences per CTA job) ----------------
__device__ void attn_phase(char* smem) {
    const int tid = threadIdx.x;
    const int h2 = tid >> 7;
    const int t2 = tid & 127;
    float* sq = (float*)smem + (size_t)h2 * 6144;
    float* sk = sq + 2048;
    float* sv = sk + 2048;

    for (int job = blockIdx.x; job < Mm / 2; job += gridDim.x) {
        int m = job * 2 + h2;
        size_t base = (size_t)m * 16 * 384;
        for (int idx = t2; idx < 2048; idx += 128) {
            int t = idx >> 7, d = idx & 127;
            size_t p = base + (size_t)t * 384 + d;
            sq[idx] = g_h[p];
            sk[idx] = g_h[p + 128];
            sv[idx] = g_h[p + 256];
        }
        __syncthreads();
        int h = t2 >> 5;
        int tq = (t2 >> 1) & 15;
        int half = t2 & 1;
        const float scale = 0.17677669529663687f;
        float sc[16];
        float mx = -1e30f;
#pragma unroll
        for (int tk = 0; tk < 16; tk++) {
            float s = 0.f;
#pragma unroll
            for (int dd = 0; dd < 16; dd++) {
                int d = half * 16 + dd;
                s += sq[tq * 128 + h * 32 + d] * sk[tk * 128 + h * 32 + d];
            }
            s += __shfl_xor_sync(0xFFFFFFFFu, s, 1);
            s *= scale;
            sc[tk] = s;
            mx = fmaxf(mx, s);
        }
        float sum = 0.f;
#pragma unroll
        for (int tk = 0; tk < 16; tk++) { sc[tk] = expf(sc[tk] - mx); sum += sc[tk]; }
        float inv = 1.f / sum;
        size_t ob = (size_t)m * 16 * 128 + (size_t)tq * 128 + h * 32 + half * 16;
#pragma unroll
        for (int dd = 0; dd < 16; dd++) {
            int d = half * 16 + dd;
            float o = 0.f;
#pragma unroll
            for (int tk = 0; tk < 16; tk++) o += sc[tk] * sv[tk * 128 + h * 32 + d];
            o *= inv;
            __nv_bfloat16 hi = __float2bfloat16(o);
            g_atth[ob + dd] = hi;
            g_attl[ob + dd] = __float2bfloat16(o - __bfloat162float(hi));
        }
        __syncthreads();
    }
}

// ---------------- params ----------------
struct MP {
    const unsigned char* ego;
    const float* positions; const float* adjacency;
    const float* gat1_W; const float* gat1_asrc; const float* gat1_adst; const float* gat1_b;
    const float* gatW; const float* gat_asrc; const float* gat_adst; const float* gat_b;
    const float* Wqkv; const float* bqkv; const float* Wo; const float* bo;
    const float* ln1_s; const float* ln1_b; const float* ln2_s; const float* ln2_b;
    const float* Wff1; const float* bff1; const float* Wff2; const float* bff2;
    float* out;
};

// ---------------- megakernel ----------------
__global__ void __launch_bounds__(256)
mega(MP p) {
    extern __shared__ char smem[];
    __shared__ unsigned sphase;
    const int tid = threadIdx.x;
    const int gstride = gridDim.x * 256;
    const int gid = blockIdx.x * 256 + tid;

    if (tid == 0) sphase = *(volatile unsigned*)&g_barphase;
    __syncthreads();

    // ---- P0: split weights + mask init + GAT0 projection/scores ----
    for (int idx = gid; idx < WTOT; idx += gstride) {
        float v;
        if (idx < OFF_QKV) {
            int i = idx >> 16, r = idx & 65535;
            int n = r >> 7, k = r & 127;
            v = p.gatW[(i << 16) + k * 512 + n];
        } else if (idx < OFF_WO) {
            int r0 = idx - OFF_QKV;
            int l = r0 / 49152;
            int rem = r0 - l * 49152;
            int n = rem >> 7, k = rem & 127;
            int s = n >> 7, nc = n & 127;
            v = p.Wqkv[((l * 3 + s) << 14) + k * 128 + nc];
        } else if (idx < OFF_FF1) {
            int r0 = idx - OFF_WO;
            int i = r0 >> 14, r = r0 & 16383;
            int n = r >> 7, k = r & 127;
            v = p.Wo[(i << 14) + k * 128 + n];
        } else if (idx < OFF_FF2) {
            int r0 = idx - OFF_FF1;
            int i = r0 >> 16, r = r0 & 65535;
            int n = r >> 7, k = r & 127;
            v = p.Wff1[(i << 16) + k * 512 + n];
        } else {
            int r0 = idx - OFF_FF2;
            int i = r0 >> 16, r = r0 & 65535;
            int n = r >> 9, k = r & 511;
            v = p.Wff2[(i << 16) + k * 128 + n];
        }
        __nv_bfloat16 h = __float2bfloat16(v);
        g_wh[idx] = h;
        g_wl[idx] = __float2bfloat16(v - __bfloat162float(h));
    }
    for (int idx = gid; idx < ROWS; idx += gstride) {
        int t = idx >> 10;
        int mm = idx & 1023;
        int b = mm >> 8;
        int n = mm & 255;
        unsigned char v = p.ego[(b * Tt + t) * 256 + n] ? 1 : 0;
        g_m[idx] = v;
        g_cnt[idx] = v ? 1 : 0;
        g_nbr[idx * MAXD] = (unsigned short)mm;
    }
    {   // GAT0: warp per row
        int wid = tid >> 5, lane = tid & 31;
        for (int row = blockIdx.x * 8 + wid; row < ROWS; row += gridDim.x * 8) {
            float x0 = p.positions[row * 2], x1 = p.positions[row * 2 + 1];
#pragma unroll
            for (int hh = 0; hh < 4; hh++) {
                int c = hh * 128 + lane * 4;
                float4 w0 = *(const float4*)(p.gat1_W + c);
                float4 w1 = *(const float4*)(p.gat1_W + 512 + c);
                float4 v;
                v.x = x0 * w0.x + x1 * w1.x;
                v.y = x0 * w0.y + x1 * w1.y;
                v.z = x0 * w0.z + x1 * w1.z;
                v.w = x0 * w0.w + x1 * w1.w;
                *(float4*)(g_h + (size_t)row * 512 + c) = v;
                float4 a1 = *(const float4*)(p.gat1_asrc + c);
                float4 a2 = *(const float4*)(p.gat1_adst + c);
                float s1 = v.x * a1.x + v.y * a1.y + v.z * a1.z + v.w * a1.w;
                float s2 = v.x * a2.x + v.y * a2.y + v.z * a2.z + v.w * a2.w;
#pragma unroll
                for (int o = 16; o; o >>= 1) {
                    s1 += __shfl_xor_sync(0xFFFFFFFFu, s1, o);
                    s2 += __shfl_xor_sync(0xFFFFFFFFu, s2, o);
                }
                if (lane == 0) {
                    g_ss[row * 4 + hh] = s1;
                    g_sd[row * 4 + hh] = s2;
                }
            }
        }
    }
    gsync(&sphase);

    // ---- P1: neighbor lists ----
    for (int tj = blockIdx.x; tj < ROWS; tj += gridDim.x) {
        if (!g_m[tj]) continue;
        int t = tj >> 10;
        int j = tj & 1023;
#pragma unroll
        for (int ch = 0; ch < 4; ch++) {
            int i = ch * 256 + tid;
            if (i == j) continue;
            float a = p.adjacency[(size_t)tj * 1024 + i];
            int ti = (t << 10) + i;
            if (a != 0.f && g_m[ti]) {
                int pos = atomicAdd(&g_cnt[ti], 1);
                if (pos < MAXD) g_nbr[(size_t)ti * MAXD + pos] = (unsigned short)j;
            }
        }
    }
    gsync(&sphase);

    // ---- P2: GAT layer-0 aggregation ----
    agg_phase(smem, p.gat1_b, g_xah, g_xal);
    gsync(&sphase);

    // ---- GAT layers 1..5 ----
    __nv_bfloat16 *curh = g_xah, *curl = g_xal, *nxth = g_xbh, *nxtl = g_xbl;
    for (int i = 0; i < 5; i++) {
        gemm_phase<0, false, true, false>(smem,
            curh, curl, g_wh + OFF_GAT + (size_t)i * 65536, g_wl + OFF_GAT + (size_t)i * 65536,
            nullptr, nullptr, g_h, nullptr, nullptr,
            p.gat_asrc + i * 512, p.gat_adst + i * 512, g_ss, g_sd,
            nullptr, nullptr, 4, 512, 128);
        gsync(&sphase);
        agg_phase(smem, p.gat_b + i * 128, nxth, nxtl);
        gsync(&sphase);
        __nv_bfloat16* t0 = curh; curh = nxth; nxth = t0;
        __nv_bfloat16* t1 = curl; curl = nxtl; nxtl = t1;
    }

    // ---- to_seq + PE ----
    for (int idx = gid; idx < ROWS * 128; idx += gstride) {
        int row = idx >> 7;
        int d = idx & 127;
        int t = row >> 10;
        int mm = row & 1023;
        float x = __bfloat162float(curh[idx]) + __bfloat162float(curl[idx]);
        float freq = expf(-(float)(d & ~1) * (9.210340371976184f / 128.f));
        float ang = (float)t * freq;
        float pe = (d & 1) ? cosf(ang) : sinf(ang);
        float v = x + pe;
        size_t sidx = ((size_t)mm * Tt + t) * Hh + d;
        g_xs[sidx] = v;
        __nv_bfloat16 hi = __float2bfloat16(v);
        g_xsh[sidx] = hi;
        g_xsl[sidx] = __float2bfloat16(v - __bfloat162float(hi));
    }
    gsync(&sphase);

    // ---- transformer layers ----
    for (int l = 0; l < NL_TR; l++) {
        size_t oq = OFF_QKV + (size_t)l * 49152;
        gemm_phase<0, false, false, false>(smem,
            g_xsh, g_xsl, g_wh + oq, g_wl + oq,
            p.bqkv + l * 384, nullptr, g_h, nullptr, nullptr,
            nullptr, nullptr, nullptr, nullptr, nullptr, nullptr, 3, 384, 128);
        gsync(&sphase);

        attn_phase(smem);
        gsync(&sphase);

        size_t owo = OFF_WO + (size_t)l * 16384;
        gemm_phase<0, true, false, true>(smem,
            g_atth, g_attl, g_wh + owo, g_wl + owo,
            p.bo + l * 128, g_xs, g_xs, g_xsh, g_xsl,
            nullptr, nullptr, nullptr, nullptr,
            p.ln1_s + l * 128, p.ln1_b + l * 128, 1, 128, 128);
        gsync(&sphase);

        size_t of1 = OFF_FF1 + (size_t)l * 65536;
        gemm_phase<1, false, false, false>(smem,
            g_xsh, g_xsl, g_wh + of1, g_wl + of1,
            p.bff1 + l * 512, nullptr, nullptr, g_ffh, g_ffl,
            nullptr, nullptr, nullptr, nullptr, nullptr, nullptr, 4, 512, 128);
        gsync(&sphase);

        size_t of2 = OFF_FF2 + (size_t)l * 65536;
        if (l == NL_TR - 1) {
            gemm_phase<0, true, false, true>(smem,
                g_ffh, g_ffl, g_wh + of2, g_wl + of2,
                p.bff2 + l * 128, g_xs, p.out, nullptr, nullptr,
                nullptr, nullptr, nullptr, nullptr,
                p.ln2_s + l * 128, p.ln2_b + l * 128, 1, 128, 512);
        } else {
            gemm_phase<0, true, false, true>(smem,
                g_ffh, g_ffl, g_wh + of2, g_wl + of2,
                p.bff2 + l * 128, g_xs, g_xs, g_xsh, g_xsl,
                nullptr, nullptr, nullptr, nullptr,
                p.ln2_s + l * 128, p.ln2_b + l * 128, 1, 128, 512);
            gsync(&sphase);
        }
    }
}

// ---------------- launcher ----------------
extern "C" void kernel_launch(void* const* d_in, const int* in_sizes, int n_in,
                              void* d_out, int out_size) {
    MP p;
    p.ego       = (const unsigned char*)d_in[0];
    p.positions = (const float*)d_in[1];
    p.adjacency = (const float*)d_in[2];
    p.gat1_W    = (const float*)d_in[3];
    p.gat1_asrc = (const float*)d_in[4];
    p.gat1_adst = (const float*)d_in[5];
    p.gat1_b    = (const float*)d_in[6];
    p.gatW      = (const float*)d_in[7];
    p.gat_asrc  = (const float*)d_in[8];
    p.gat_adst  = (const float*)d_in[9];
    p.gat_b     = (const float*)d_in[10];
    p.Wqkv      = (const float*)d_in[11];
    p.bqkv      = (const float*)d_in[12];
    p.Wo        = (const float*)d_in[13];
    p.bo        = (const float*)d_in[14];
    p.ln1_s     = (const float*)d_in[15];
    p.ln1_b     = (const float*)d_in[16];
    p.ln2_s     = (const float*)d_in[17];
    p.ln2_b     = (const float*)d_in[18];
    p.Wff1      = (const float*)d_in[19];
    p.bff1      = (const float*)d_in[20];
    p.Wff2      = (const float*)d_in[21];
    p.bff2      = (const float*)d_in[22];
    p.out       = (float*)d_out;

    static int configured = 0;
    if (!configured) {
        cudaFuncSetAttribute(mega, cudaFuncAttributeMaxDynamicSharedMemorySize, GSM_TOTAL);
        configured = 1;
    }
    mega<<<NCTA, 256, GSM_TOTAL>>>(p);
}

// round 7
// speedup vs baseline: 1.9185x; 1.9185x over previous
#include <cuda_runtime.h>
#include <cuda_bf16.h>
#include <math.h>

// Problem dims
#define Tt 16
#define Mm 1024
#define Hh 128
#define ROWS 16384
#define MAXD 128
#define NL_TR 5

// ---------------- scratch (device globals; no allocations) ----------------
__device__ float g_h[ROWS * 512];          // GAT projections (512) / transformer QKV (384) fp32
__device__ float g_ss[ROWS * 4];
__device__ float g_sd[ROWS * 4];
__device__ unsigned char g_m[ROWS];
__device__ int g_cnt[ROWS];
__device__ unsigned short g_nbr[ROWS * MAXD];
__device__ float g_xs[ROWS * Hh];
__device__ __nv_bfloat16 g_xah[ROWS * Hh], g_xal[ROWS * Hh];
__device__ __nv_bfloat16 g_xbh[ROWS * Hh], g_xbl[ROWS * Hh];
__device__ __nv_bfloat16 g_xsh[ROWS * Hh], g_xsl[ROWS * Hh];
__device__ __nv_bfloat16 g_atth[ROWS * Hh], g_attl[ROWS * Hh];
__device__ __nv_bfloat16 g_ffh[ROWS * 512], g_ffl[ROWS * 512];

#define WTOT 1310720
#define OFF_GAT 0
#define OFF_QKV 327680
#define OFF_WO  573440
#define OFF_FF1 655360
#define OFF_FF2 983040
__device__ __nv_bfloat16 g_wh[WTOT];
__device__ __nv_bfloat16 g_wl[WTOT];

__device__ __forceinline__ unsigned smem_u32(const void* p) {
    unsigned a;
    asm("{ .reg .u64 t; cvta.to.shared.u64 t, %1; cvt.u32.u64 %0, t; }" : "=r"(a) : "l"(p));
    return a;
}
__device__ __forceinline__ void ldmat4(unsigned& r0, unsigned& r1, unsigned& r2, unsigned& r3, unsigned addr) {
    asm volatile("ldmatrix.sync.aligned.m8n8.x4.shared.b16 {%0,%1,%2,%3}, [%4];"
        : "=r"(r0), "=r"(r1), "=r"(r2), "=r"(r3) : "r"(addr));
}
__device__ __forceinline__ void mma16816(float* c, unsigned a0, unsigned a1, unsigned a2, unsigned a3,
                                         unsigned b0, unsigned b1) {
    asm volatile("mma.sync.aligned.m16n8k16.row.col.f32.bf16.bf16.f32 "
        "{%0,%1,%2,%3}, {%4,%5,%6,%7}, {%8,%9}, {%0,%1,%2,%3};"
        : "+f"(c[0]), "+f"(c[1]), "+f"(c[2]), "+f"(c[3])
        : "r"(a0), "r"(a1), "r"(a2), "r"(a3), "r"(b0), "r"(b1));
}
__device__ __forceinline__ void cpa16(unsigned dst, const void* src) {
    asm volatile("cp.async.ca.shared.global [%0], [%1], 16;" :: "r"(dst), "l"(src));
}
#define CPA_COMMIT() asm volatile("cp.async.commit_group;" ::: "memory")
#define CPA_WAIT1() asm volatile("cp.async.wait_group 1;" ::: "memory")
#define CPA_WAIT0() asm volatile("cp.async.wait_group 0;" ::: "memory")

__device__ __forceinline__ unsigned pack_hi2(float a, float b) {
    __nv_bfloat16 ha = __float2bfloat16(a), hb = __float2bfloat16(b);
    return (unsigned)__bfloat16_as_ushort(ha) | ((unsigned)__bfloat16_as_ushort(hb) << 16);
}
__device__ __forceinline__ unsigned pack_lo2(float a, float b) {
    __nv_bfloat16 ha = __float2bfloat16(a), hb = __float2bfloat16(b);
    float la = a - __bfloat162float(ha), lb2 = b - __bfloat162float(hb);
    __nv_bfloat16 qa = __float2bfloat16(la), qb = __float2bfloat16(lb2);
    return (unsigned)__bfloat16_as_ushort(qa) | ((unsigned)__bfloat16_as_ushort(qb) << 16);
}

// SMEM: 2 stages x 4 planes, each 128 rows x 32 bf16 (80B stride: 64B data + 16B pad)
// 80/16 = 5, gcd(5,8)=1 -> ldmatrix 8-row reads hit 8 distinct 16B banks (conflict-free).
#define TROW 80
#define PBUF (128 * TROW)       // 10240
#define STAGE (4 * PBUF)        // 40960
#define P_AHI 0
#define P_ALO PBUF
#define P_BHI (2 * PBUF)
#define P_BLO (3 * PBUF)
#define GSM_TOTAL (2 * STAGE)   // 81920 -> 2 CTAs/SM (epilogue stage 128*132*4=67584 fits)

// ---------------- HMMA GEMM, planar bf16 A/B, cp.async double-buffered, 2 CTA/SM ----------------
template <int ACT, bool RESID, bool SCORES, bool LNORM>
__global__ void __launch_bounds__(256, 2)
gemm_tc(const __nv_bfloat16* __restrict__ Ah, const __nv_bfloat16* __restrict__ Al,
        const __nv_bfloat16* __restrict__ Bh, const __nv_bfloat16* __restrict__ Bl,
        const float* __restrict__ bias, const float* __restrict__ Rr,
        float* __restrict__ C, __nv_bfloat16* __restrict__ Ch, __nv_bfloat16* __restrict__ Cl,
        const float* __restrict__ asrc, const float* __restrict__ adst,
        float* __restrict__ gss, float* __restrict__ gsd,
        const float* __restrict__ ls, const float* __restrict__ lb, int Nt, int Kt) {
    extern __shared__ char smem[];
    const unsigned sb = smem_u32(smem);
    const int tid = threadIdx.x;
    const int wid = tid >> 5, lane = tid & 31;
    const int wr = wid >> 1, wc = wid & 1;
    const int row0 = blockIdx.y * 128;
    const int col0 = blockIdx.x * 128;

    float acc[2][8][4];
#pragma unroll
    for (int mt = 0; mt < 2; mt++)
#pragma unroll
        for (int nt = 0; nt < 8; nt++)
#pragma unroll
            for (int e = 0; e < 4; e++) acc[mt][nt][e] = 0.f;

    const int ltile = lane >> 3, lrow = lane & 7;
    const int nch = Kt >> 5;

#define LOAD_CHUNK(cidx, s) do { \
    unsigned base = sb + (s) * STAGE; \
    _Pragma("unroll") \
    for (int j = 0; j < 2; j++) { \
        int i = tid + j * 256; \
        int rr = i >> 2, qq = i & 3; \
        unsigned off = (unsigned)(rr * TROW + qq * 16); \
        size_t ga = (size_t)(row0 + rr) * Kt + (cidx) * 32 + qq * 8; \
        size_t gb = (size_t)(col0 + rr) * Kt + (cidx) * 32 + qq * 8; \
        cpa16(base + P_AHI + off, Ah + ga); \
        cpa16(base + P_ALO + off, Al + ga); \
        cpa16(base + P_BHI + off, Bh + gb); \
        cpa16(base + P_BLO + off, Bl + gb); \
    } \
} while (0)

    LOAD_CHUNK(0, 0);
    CPA_COMMIT();

    for (int c = 0; c < nch; c++) {
        if (c + 1 < nch) {
            LOAD_CHUNK(c + 1, (c + 1) & 1);
            CPA_COMMIT();
            CPA_WAIT1();
        } else {
            CPA_WAIT0();
        }
        __syncthreads();
        unsigned base = sb + (c & 1) * STAGE;
#pragma unroll
        for (int ks = 0; ks < 2; ks++) {
            unsigned ah[2][4], al[2][4];
#pragma unroll
            for (int mt = 0; mt < 2; mt++) {
                int row = wr * 32 + mt * 16 + lrow + (ltile & 1) * 8;
                int kcol = ks * 16 + (ltile >> 1) * 8;
                unsigned off = (unsigned)(row * TROW + kcol * 2);
                ldmat4(ah[mt][0], ah[mt][1], ah[mt][2], ah[mt][3], base + P_AHI + off);
                ldmat4(al[mt][0], al[mt][1], al[mt][2], al[mt][3], base + P_ALO + off);
            }
#pragma unroll
            for (int g = 0; g < 4; g++) {
                int n = wc * 64 + g * 16 + lrow + (ltile >> 1) * 8;
                int kcol = ks * 16 + (ltile & 1) * 8;
                unsigned off = (unsigned)(n * TROW + kcol * 2);
                unsigned bh[4], bl[4];
                ldmat4(bh[0], bh[1], bh[2], bh[3], base + P_BHI + off);
                ldmat4(bl[0], bl[1], bl[2], bl[3], base + P_BLO + off);
#pragma unroll
                for (int mt = 0; mt < 2; mt++)
#pragma unroll
                    for (int half = 0; half < 2; half++) {
                        float* cc = acc[mt][g * 2 + half];
                        mma16816(cc, ah[mt][0], ah[mt][1], ah[mt][2], ah[mt][3],
                                 bh[half * 2], bh[half * 2 + 1]);
                        mma16816(cc, ah[mt][0], ah[mt][1], ah[mt][2], ah[mt][3],
                                 bl[half * 2], bl[half * 2 + 1]);
                        mma16816(cc, al[mt][0], al[mt][1], al[mt][2], al[mt][3],
                                 bh[half * 2], bh[half * 2 + 1]);
                    }
            }
        }
        __syncthreads();
    }
#undef LOAD_CHUNK

    // stage accumulators to smem (stride 132 floats) for coalesced epilogue
    float* stage = (float*)smem;
#pragma unroll
    for (int mt = 0; mt < 2; mt++)
#pragma unroll
        for (int nt = 0; nt < 8; nt++) {
            int row = wr * 32 + mt * 16 + (lane >> 2);
            int col = wc * 64 + nt * 8 + (lane & 3) * 2;
            float2 v0 = make_float2(acc[mt][nt][0], acc[mt][nt][1]);
            float2 v1 = make_float2(acc[mt][nt][2], acc[mt][nt][3]);
            *(float2*)(stage + (size_t)row * 132 + col) = v0;
            *(float2*)(stage + (size_t)(row + 8) * 132 + col) = v1;
        }
    __syncthreads();

    if (LNORM) {
        const int c = lane * 4;
        float4 bb = *(const float4*)(bias + c);
        float4 sv = *(const float4*)(ls + c);
        float4 bv = *(const float4*)(lb + c);
#pragma unroll 4
        for (int rr = 0; rr < 16; rr++) {
            int r = wid * 16 + rr;
            float4 v = *(float4*)(stage + (size_t)r * 132 + c);
            float4 res = *(const float4*)(Rr + (size_t)(row0 + r) * 128 + c);
            v.x += bb.x + res.x; v.y += bb.y + res.y;
            v.z += bb.z + res.z; v.w += bb.w + res.w;
            float s = v.x + v.y + v.z + v.w;
#pragma unroll
            for (int o = 16; o; o >>= 1) s += __shfl_xor_sync(0xFFFFFFFFu, s, o);
            float mean = s * (1.f / 128.f);
            float dx = v.x - mean, dy = v.y - mean, dz = v.z - mean, dw = v.w - mean;
            float qq = dx * dx + dy * dy + dz * dz + dw * dw;
#pragma unroll
            for (int o = 16; o; o >>= 1) qq += __shfl_xor_sync(0xFFFFFFFFu, qq, o);
            float rstd = rsqrtf(qq * (1.f / 128.f) + 1e-5f);
            float4 ov;
            ov.x = dx * rstd * sv.x + bv.x;
            ov.y = dy * rstd * sv.y + bv.y;
            ov.z = dz * rstd * sv.z + bv.z;
            ov.w = dw * rstd * sv.w + bv.w;
            if (C) *(float4*)(C + (size_t)(row0 + r) * 128 + c) = ov;
            if (Ch) {
                uint2 uh, ul;
                uh.x = pack_hi2(ov.x, ov.y); uh.y = pack_hi2(ov.z, ov.w);
                ul.x = pack_lo2(ov.x, ov.y); ul.y = pack_lo2(ov.z, ov.w);
                *(uint2*)(Ch + (size_t)(row0 + r) * 128 + c) = uh;
                *(uint2*)(Cl + (size_t)(row0 + r) * 128 + c) = ul;
            }
        }
    } else {
        for (int i = tid; i < 128 * 32; i += 256) {
            int r = i >> 5, q = i & 31;
            int c = q * 4;
            float4 v = *(float4*)(stage + (size_t)r * 132 + c);
            if (bias) {
                v.x += bias[col0 + c];
                v.y += bias[col0 + c + 1];
                v.z += bias[col0 + c + 2];
                v.w += bias[col0 + c + 3];
            }
            if (RESID) {
                float4 rr = *(const float4*)(Rr + (size_t)(row0 + r) * Nt + col0 + c);
                v.x += rr.x; v.y += rr.y; v.z += rr.z; v.w += rr.w;
            }
            if (ACT == 1) {
                v.x = fmaxf(v.x, 0.f); v.y = fmaxf(v.y, 0.f);
                v.z = fmaxf(v.z, 0.f); v.w = fmaxf(v.w, 0.f);
            }
            if (C) *(float4*)(C + (size_t)(row0 + r) * Nt + col0 + c) = v;
            if (Ch) {
                uint2 uh, ul;
                uh.x = pack_hi2(v.x, v.y); uh.y = pack_hi2(v.z, v.w);
                ul.x = pack_lo2(v.x, v.y); ul.y = pack_lo2(v.z, v.w);
                *(uint2*)(Ch + (size_t)(row0 + r) * Nt + col0 + c) = uh;
                *(uint2*)(Cl + (size_t)(row0 + r) * Nt + col0 + c) = ul;
            }
        }
    }

    if (SCORES && tid < 128) {
        int r = tid;
        float s1 = 0.f, s2 = 0.f;
        const float* as = asrc + col0;
        const float* ad = adst + col0;
        const float* sp = stage + (size_t)r * 132;
#pragma unroll 8
        for (int c = 0; c < 128; c++) {
            float hv = sp[c];
            s1 += hv * as[c];
            s2 += hv * ad[c];
        }
        gss[(size_t)(row0 + r) * 4 + blockIdx.x] = s1;
        gsd[(size_t)(row0 + r) * 4 + blockIdx.x] = s2;
    }
}

// ---------------- weight pre-split; QKV packed per-layer [384, 128] ----------------
__global__ void split_weights(const float* __restrict__ gatW, const float* __restrict__ Wqkv,
                              const float* __restrict__ Wo, const float* __restrict__ Wff1,
                              const float* __restrict__ Wff2) {
    int idx = blockIdx.x * 256 + threadIdx.x;
    if (idx >= WTOT) return;
    float v;
    if (idx < OFF_QKV) {
        int i = idx >> 16, r = idx & 65535;
        int n = r >> 7, k = r & 127;
        v = gatW[(i << 16) + k * 512 + n];
    } else if (idx < OFF_WO) {
        int r0 = idx - OFF_QKV;
        int l = r0 / 49152;
        int rem = r0 - l * 49152;
        int n = rem >> 7, k = rem & 127;
        int s = n >> 7, nc = n & 127;
        v = Wqkv[((l * 3 + s) << 14) + k * 128 + nc];
    } else if (idx < OFF_FF1) {
        int r0 = idx - OFF_WO;
        int i = r0 >> 14, r = r0 & 16383;
        int n = r >> 7, k = r & 127;
        v = Wo[(i << 14) + k * 128 + n];
    } else if (idx < OFF_FF2) {
        int r0 = idx - OFF_FF1;
        int i = r0 >> 16, r = r0 & 65535;
        int n = r >> 7, k = r & 127;
        v = Wff1[(i << 16) + k * 512 + n];
    } else {
        int r0 = idx - OFF_FF2;
        int i = r0 >> 16, r = r0 & 65535;
        int n = r >> 9, k = r & 511;
        v = Wff2[(i << 16) + k * 128 + n];
    }
    __nv_bfloat16 h = __float2bfloat16(v);
    g_wh[idx] = h;
    g_wl[idx] = __float2bfloat16(v - __bfloat162float(h));
}

// ---------------- mask + self-loop init ----------------
__global__ void mask_init(const unsigned char* __restrict__ ego) {
    int idx = blockIdx.x * 256 + threadIdx.x;
    if (idx >= ROWS) return;
    int t = idx >> 10;
    int mm = idx & 1023;
    int b = mm >> 8;
    int n = mm & 255;
    unsigned char v = ego[(b * Tt + t) * 256 + n] ? 1 : 0;
    g_m[idx] = v;
    g_cnt[idx] = v ? 1 : 0;
    g_nbr[idx * MAXD] = (unsigned short)mm;
}

// ---------------- neighbor-list build ----------------
__global__ void build_nbr(const float* __restrict__ A) {
    int tj = blockIdx.x >> 2;
    int i = ((blockIdx.x & 3) << 8) + threadIdx.x;
    if (!g_m[tj]) return;
    int t = tj >> 10;
    int j = tj & 1023;
    if (i == j) return;
    float a = A[(size_t)tj * 1024 + i];
    int ti = (t << 10) + i;
    if (a != 0.f && g_m[ti]) {
        int pos = atomicAdd(&g_cnt[ti], 1);
        if (pos < MAXD) g_nbr[ti * MAXD + pos] = (unsigned short)j;
    }
}

// ---------------- GAT layer-0: fused projection (FIN=2) + src/dst scores ----------------
__global__ void gat0_fused(const float* __restrict__ x, const float* __restrict__ W,
                           const float* __restrict__ asrc, const float* __restrict__ adst) {
    int row = blockIdx.x;
    int d = threadIdx.x;
    int lane = d & 31, wrp = d >> 5;
    float x0 = x[row * 2], x1 = x[row * 2 + 1];
    __shared__ float red[4][8];
    float s1[4], s2[4];
#pragma unroll
    for (int hh = 0; hh < 4; hh++) {
        int c = hh * 128 + d;
        float v = x0 * W[c] + x1 * W[512 + c];
        g_h[(size_t)row * 512 + c] = v;
        s1[hh] = v * asrc[c];
        s2[hh] = v * adst[c];
    }
#pragma unroll
    for (int hh = 0; hh < 4; hh++) {
#pragma unroll
        for (int o = 16; o; o >>= 1) {
            s1[hh] += __shfl_xor_sync(0xFFFFFFFFu, s1[hh], o);
            s2[hh] += __shfl_xor_sync(0xFFFFFFFFu, s2[hh], o);
        }
    }
    if (lane == 0) {
#pragma unroll
        for (int hh = 0; hh < 4; hh++) {
            red[wrp][hh] = s1[hh];
            red[wrp][4 + hh] = s2[hh];
        }
    }
    __syncthreads();
    if (d < 8) {
        float s = red[0][d] + red[1][d] + red[2][d] + red[3][d];
        if (d < 4) g_ss[row * 4 + d] = s;
        else g_sd[row * 4 + (d - 4)] = s;
    }
}

// ---------------- sparse segment-softmax + aggregation -> planar bf16 ----------------
__global__ void gat_agg(const float* __restrict__ bias,
                        __nv_bfloat16* __restrict__ xh, __nv_bfloat16* __restrict__ xl) {
    int row = blockIdx.x;
    int tid = threadIdx.x;
    if (!g_m[row]) {
        xh[(size_t)row * 128 + tid] = __float2bfloat16(0.f);
        xl[(size_t)row * 128 + tid] = __float2bfloat16(0.f);
        return;
    }
    int t = row >> 10;

    __shared__ unsigned short nb[MAXD];
    __shared__ float w[4][MAXD];

    int cnt = g_cnt[row];
    if (cnt > MAXD) cnt = MAXD;
    if (tid < cnt) nb[tid] = g_nbr[(size_t)row * MAXD + tid];

    if (tid < cnt) {
        int jr = (t << 10) + nb[tid];
#pragma unroll
        for (int hh = 0; hh < 4; hh++) {
            float z = g_sd[row * 4 + hh] + g_ss[jr * 4 + hh];
            w[hh][tid] = (z > 0.f) ? z : 0.2f * z;
        }
    } else {
#pragma unroll
        for (int hh = 0; hh < 4; hh++) w[hh][tid] = -INFINITY;
    }
    __syncthreads();

    {
        int wh = tid >> 5, lane = tid & 31;
        float v0 = w[wh][lane], v1 = w[wh][lane + 32], v2 = w[wh][lane + 64], v3 = w[wh][lane + 96];
        float mx = fmaxf(fmaxf(v0, v1), fmaxf(v2, v3));
#pragma unroll
        for (int o = 16; o; o >>= 1) mx = fmaxf(mx, __shfl_xor_sync(0xFFFFFFFFu, mx, o));
        float e0 = expf(v0 - mx), e1 = expf(v1 - mx), e2 = expf(v2 - mx), e3 = expf(v3 - mx);
        float s = e0 + e1 + e2 + e3;
#pragma unroll
        for (int o = 16; o; o >>= 1) s += __shfl_xor_sync(0xFFFFFFFFu, s, o);
        float inv = 1.f / s;
        w[wh][lane] = e0 * inv;
        w[wh][lane + 32] = e1 * inv;
        w[wh][lane + 64] = e2 * inv;
        w[wh][lane + 96] = e3 * inv;
    }
    __syncthreads();

    float acc0 = 0.f, acc1 = 0.f, acc2 = 0.f, acc3 = 0.f;
    const float* hbase = g_h + (((size_t)(t << 10)) << 9) + tid;
    int j = 0;
    for (; j + 4 <= cnt; j += 4) {
        const float* p0 = hbase + ((size_t)nb[j] << 9);
        const float* p1 = hbase + ((size_t)nb[j + 1] << 9);
        const float* p2 = hbase + ((size_t)nb[j + 2] << 9);
        const float* p3 = hbase + ((size_t)nb[j + 3] << 9);
#pragma unroll
        for (int hh = 0; hh < 4; hh++) {
            acc0 += w[hh][j] * p0[hh << 7];
            acc1 += w[hh][j + 1] * p1[hh << 7];
            acc2 += w[hh][j + 2] * p2[hh << 7];
            acc3 += w[hh][j + 3] * p3[hh << 7];
        }
    }
    for (; j < cnt; j++) {
        const float* p0 = hbase + ((size_t)nb[j] << 9);
#pragma unroll
        for (int hh = 0; hh < 4; hh++) acc0 += w[hh][j] * p0[hh << 7];
    }
    float o = (acc0 + acc1 + acc2 + acc3) * 0.25f + bias[tid];
    o = fmaxf(o, 0.f);
    __nv_bfloat16 hi = __float2bfloat16(o);
    xh[(size_t)row * 128 + tid] = hi;
    xl[(size_t)row * 128 + tid] = __float2bfloat16(o - __bfloat162float(hi));
}

// ---------------- transpose to sequence layout + PE ----------------
__global__ void to_seq(const __nv_bfloat16* __restrict__ xh, const __nv_bfloat16* __restrict__ xl) {
    int idx = blockIdx.x * 256 + threadIdx.x;
    int row = idx >> 7;
    int d = idx & 127;
    int t = row >> 10;
    int mm = row & 1023;
    float x = __bfloat162float(xh[idx]) + __bfloat162float(xl[idx]);
    float freq = expf(-(float)(d & ~1) * (9.210340371976184f / 128.f));
    float ang = (float)t * freq;
    float pe = (d & 1) ? cosf(ang) : sinf(ang);
    float v = x + pe;
    size_t sidx = ((size_t)mm * Tt + t) * Hh + d;
    g_xs[sidx] = v;
    __nv_bfloat16 hi = __float2bfloat16(v);
    g_xsh[sidx] = hi;
    g_xsl[sidx] = __float2bfloat16(v - __bfloat162float(hi));
}

// ---------------- per-sequence attention (T=16, 4 heads of 32), packed QKV ----------------
__global__ void attn_kernel(const float* __restrict__ QKV,
                            __nv_bfloat16* __restrict__ Oh, __nv_bfloat16* __restrict__ Ol) {
    __shared__ float sq[16][128], sk[16][128], sv[16][128];
    int m = blockIdx.x;
    int tid = threadIdx.x;
    size_t base = (size_t)m * 16 * 384;
    for (int idx = tid; idx < 2048; idx += 128) {
        int t = idx >> 7, d = idx & 127;
        size_t p = base + (size_t)t * 384 + d;
        sq[t][d] = QKV[p];
        sk[t][d] = QKV[p + 128];
        sv[t][d] = QKV[p + 256];
    }
    __syncthreads();
    int h = tid >> 5;
    int tq = (tid >> 1) & 15;
    int half = tid & 1;
    const float scale = 0.17677669529663687f;
    float sc[16];
    float mx = -1e30f;
#pragma unroll
    for (int tk = 0; tk < 16; tk++) {
        float s = 0.f;
#pragma unroll
        for (int dd = 0; dd < 16; dd++) {
            int d = half * 16 + dd;
            s += sq[tq][h * 32 + d] * sk[tk][h * 32 + d];
        }
        s += __shfl_xor_sync(0xFFFFFFFFu, s, 1);
        s *= scale;
        sc[tk] = s;
        mx = fmaxf(mx, s);
    }
    float sum = 0.f;
#pragma unroll
    for (int tk = 0; tk < 16; tk++) { sc[tk] = expf(sc[tk] - mx); sum += sc[tk]; }
    float inv = 1.f / sum;
    size_t ob = (size_t)m * 16 * 128 + (size_t)tq * 128 + h * 32 + half * 16;
#pragma unroll
    for (int dd = 0; dd < 16; dd++) {
        int d = half * 16 + dd;
        float o = 0.f;
#pragma unroll
        for (int tk = 0; tk < 16; tk++) o += sc[tk] * sv[tk][h * 32 + d];
        o *= inv;
        __nv_bfloat16 hi = __float2bfloat16(o);
        Oh[ob + dd] = hi;
        Ol[ob + dd] = __float2bfloat16(o - __bfloat162float(hi));
    }
}

// ---------------- launcher ----------------
extern "C" void kernel_launch(void* const* d_in, const int* in_sizes, int n_in,
                              void* d_out, int out_size) {
    const unsigned char* ego = (const unsigned char*)d_in[0];
    const float* positions  = (const float*)d_in[1];
    const float* adjacency  = (const float*)d_in[2];
    const float* gat1_W     = (const float*)d_in[3];
    const float* gat1_asrc  = (const float*)d_in[4];
    const float* gat1_adst  = (const float*)d_in[5];
    const float* gat1_b     = (const float*)d_in[6];
    const float* gatW       = (const float*)d_in[7];
    const float* gat_asrc   = (const float*)d_in[8];
    const float* gat_adst   = (const float*)d_in[9];
    const float* gat_b      = (const float*)d_in[10];
    const float* Wqkv       = (const float*)d_in[11];
    const float* bqkv       = (const float*)d_in[12];
    const float* Wo         = (const float*)d_in[13];
    const float* bo         = (const float*)d_in[14];
    const float* ln1_s      = (const float*)d_in[15];
    const float* ln1_b      = (const float*)d_in[16];
    const float* ln2_s      = (const float*)d_in[17];
    const float* ln2_b      = (const float*)d_in[18];
    const float* Wff1       = (const float*)d_in[19];
    const float* bff1       = (const float*)d_in[20];
    const float* Wff2       = (const float*)d_in[21];
    const float* bff2       = (const float*)d_in[22];
    float* out = (float*)d_out;

    float *h, *xs, *ss, *sd;
    __nv_bfloat16 *wh, *wl, *xah, *xal, *xbh, *xbl, *xsh, *xsl, *atth, *attl, *ffh, *ffl;
    cudaGetSymbolAddress((void**)&h,    g_h);
    cudaGetSymbolAddress((void**)&xs,   g_xs);
    cudaGetSymbolAddress((void**)&ss,   g_ss);
    cudaGetSymbolAddress((void**)&sd,   g_sd);
    cudaGetSymbolAddress((void**)&wh,   g_wh);
    cudaGetSymbolAddress((void**)&wl,   g_wl);
    cudaGetSymbolAddress((void**)&xah,  g_xah);
    cudaGetSymbolAddress((void**)&xal,  g_xal);
    cudaGetSymbolAddress((void**)&xbh,  g_xbh);
    cudaGetSymbolAddress((void**)&xbl,  g_xbl);
    cudaGetSymbolAddress((void**)&xsh,  g_xsh);
    cudaGetSymbolAddress((void**)&xsl,  g_xsl);
    cudaGetSymbolAddress((void**)&atth, g_atth);
    cudaGetSymbolAddress((void**)&attl, g_attl);
    cudaGetSymbolAddress((void**)&ffh,  g_ffh);
    cudaGetSymbolAddress((void**)&ffl,  g_ffl);

    cudaFuncSetAttribute(gemm_tc<0, false, true,  false>, cudaFuncAttributeMaxDynamicSharedMemorySize, GSM_TOTAL);
    cudaFuncSetAttribute(gemm_tc<0, false, false, false>, cudaFuncAttributeMaxDynamicSharedMemorySize, GSM_TOTAL);
    cudaFuncSetAttribute(gemm_tc<0, true,  false, true >, cudaFuncAttributeMaxDynamicSharedMemorySize, GSM_TOTAL);
    cudaFuncSetAttribute(gemm_tc<1, false, false, false>, cudaFuncAttributeMaxDynamicSharedMemorySize, GSM_TOTAL);

    split_weights<<<(WTOT + 255) / 256, 256>>>(gatW, Wqkv, Wo, Wff1, Wff2);
    mask_init<<<ROWS / 256, 256>>>(ego);
    build_nbr<<<ROWS * 4, 256>>>(adjacency);

    // GAT layer 0 (FIN=2)
    gat0_fused<<<ROWS, 128>>>(positions, gat1_W, gat1_asrc, gat1_adst);
    gat_agg<<<ROWS, 128>>>(gat1_b, xah, xal);

    // GAT layers 1..5
    __nv_bfloat16 *curh = xah, *curl = xal, *nxth = xbh, *nxtl = xbl;
    for (int i = 0; i < 5; i++) {
        dim3 gp(4, ROWS / 128);
        gemm_tc<0, false, true, false><<<gp, 256, GSM_TOTAL>>>(
            curh, curl, wh + OFF_GAT + (size_t)i * 65536, wl + OFF_GAT + (size_t)i * 65536,
            nullptr, nullptr, h, nullptr, nullptr,
            gat_asrc + i * 512, gat_adst + i * 512, ss, sd, nullptr, nullptr, 512, 128);
        gat_agg<<<ROWS, 128>>>(gat_b + i * 128, nxth, nxtl);
        __nv_bfloat16* t0 = curh; curh = nxth; nxth = t0;
        __nv_bfloat16* t1 = curl; curl = nxtl; nxtl = t1;
    }

    to_seq<<<ROWS * 128 / 256, 256>>>(curh, curl);

    dim3 g1(1, ROWS / 128);
    dim3 g2(4, ROWS / 128);
    dim3 gq(3, ROWS / 128);
    for (int l = 0; l < NL_TR; l++) {
        size_t oq = OFF_QKV + (size_t)l * 49152;
        gemm_tc<0, false, false, false><<<gq, 256, GSM_TOTAL>>>(
            xsh, xsl, wh + oq, wl + oq,
            bqkv + l * 384, nullptr, h, nullptr, nullptr,
            nullptr, nullptr, nullptr, nullptr, nullptr, nullptr, 384, 128);
        attn_kernel<<<Mm, 128>>>(h, atth, attl);
        size_t owo = OFF_WO + (size_t)l * 16384;
        gemm_tc<0, true, false, true><<<g1, 256, GSM_TOTAL>>>(
            atth, attl, wh + owo, wl + owo,
            bo + l * 128, xs, xs, xsh, xsl,
            nullptr, nullptr, nullptr, nullptr,
            ln1_s + l * 128, ln1_b + l * 128, 128, 128);
        size_t of1 = OFF_FF1 + (size_t)l * 65536;
        gemm_tc<1, false, false, false><<<g2, 256, GSM_TOTAL>>>(
            xsh, xsl, wh + of1, wl + of1,
            bff1 + l * 512, nullptr, nullptr, ffh, ffl,
            nullptr, nullptr, nullptr, nullptr, nullptr, nullptr, 512, 128);
        size_t of2 = OFF_FF2 + (size_t)l * 65536;
        if (l == NL_TR - 1) {
            gemm_tc<0, true, false, true><<<g1, 256, GSM_TOTAL>>>(
                ffh, ffl, wh + of2, wl + of2,
                bff2 + l * 128, xs, out, nullptr, nullptr,
                nullptr, nullptr, nullptr, nullptr,
                ln2_s + l * 128, ln2_b + l * 128, 128, 512);
        } else {
            gemm_tc<0, true, false, true><<<g1, 256, GSM_TOTAL>>>(
                ffh, ffl, wh + of2, wl + of2,
                bff2 + l * 128, xs, xs, xsh, xsl,
                nullptr, nullptr, nullptr, nullptr,
                ln2_s + l * 128, ln2_b + l * 128, 128, 512);
        }
    }
}